// round 1
// baseline (speedup 1.0000x reference)
#include <cuda_runtime.h>

#define Bq 8
#define Cc 128
#define Dd 512
#define Tt 8000
#define Ll 4
#define EPSf 1e-5f
#define NBTf 64000.0f

typedef unsigned long long ull;

// ---------------- device scratch (no allocations allowed) ----------------
__device__ float g_y1[Bq * Dd * Tt];   // post conv1+prelu   (131 MB)
__device__ float g_z [Bq * Dd * Tt];   // post dwconv+prelu  (131 MB)
__device__ float g_h [Bq * Cc * Tt];   // inter-layer C-space (33 MB)
__device__ float g_sum[Dd];
__device__ float g_sumsq[Dd];
__device__ float g_scale1[Dd];
__device__ float g_shift1[Dd];
__device__ float g_scale2[Dd];
__device__ float g_shift2[Dd];
__device__ float g_biaseff[Cc];

// ---------------- packed f32x2 helpers (FFMA2 full-rate path) ----------------
__device__ __forceinline__ ull pack2(float x, float y) {
    ull r; asm("mov.b64 %0, {%1, %2};" : "=l"(r) : "f"(x), "f"(y)); return r;
}
__device__ __forceinline__ void fma2(ull& d, ull a, ull b) {
    asm("fma.rn.f32x2 %0, %1, %2, %0;" : "+l"(d) : "l"(a), "l"(b));
}
__device__ __forceinline__ float2 unpack2(ull v) {
    float2 f; asm("mov.b64 {%0, %1}, %2;" : "=f"(f.x), "=f"(f.y) : "l"(v)); return f;
}

// ============================================================================
// Kernel 1: 1x1 conv C->D (+bias, PReLU) with fused BN-stat accumulation.
// Y[b,d,t] = prelu( sum_c W[d,c]*H[b,c,t] + b1[d] )
// Tiles: BM=64 (d), BN=64 (t), BK=64. 256 threads, 4x4 micro-tile, f32x2 FMAs.
// ============================================================================
__global__ __launch_bounds__(256) void gemm1_kernel(
    const float* __restrict__ Xin, const float* __restrict__ W,
    const float* __restrict__ bias1, const float* __restrict__ a1p, int use_gh)
{
    __shared__ float As[64][65];   // As[k][m] = W[d0+m][c0+k]
    __shared__ float Bs[64][64];   // Bs[k][n] = H[c0+k][t0+n]

    const int tid = threadIdx.x;
    const int row = tid >> 4;      // 0..15 (d groups of 4)
    const int col = tid & 15;      // 0..15 (t groups of 4)
    const int t0 = blockIdx.x * 64;
    const int d0 = blockIdx.y * 64;
    const int b  = blockIdx.z;

    const float* H = (use_gh ? (const float*)g_h : Xin) + b * Cc * Tt;

    ull acc[4][2];
#pragma unroll
    for (int i = 0; i < 4; i++) { acc[i][0] = 0ULL; acc[i][1] = 0ULL; }

    for (int c0 = 0; c0 < Cc; c0 += 64) {
#pragma unroll
        for (int p = 0; p < 4; p++) {                 // load W tile (transposed)
            int idx = p * 256 + tid;
            int k4 = idx & 15, m = idx >> 4;
            float4 v = *(const float4*)(W + (d0 + m) * Cc + c0 + k4 * 4);
            As[k4 * 4 + 0][m] = v.x;
            As[k4 * 4 + 1][m] = v.y;
            As[k4 * 4 + 2][m] = v.z;
            As[k4 * 4 + 3][m] = v.w;
        }
#pragma unroll
        for (int p = 0; p < 4; p++) {                 // load H tile
            int idx = p * 256 + tid;
            int n4 = idx & 15, kk = idx >> 4;
            *(float4*)(&Bs[kk][n4 * 4]) =
                *(const float4*)(H + (c0 + kk) * Tt + t0 + n4 * 4);
        }
        __syncthreads();
#pragma unroll 8
        for (int k = 0; k < 64; k++) {
            float4 bv = *(const float4*)(&Bs[k][col * 4]);
            ull b01 = pack2(bv.x, bv.y), b23 = pack2(bv.z, bv.w);
#pragma unroll
            for (int i = 0; i < 4; i++) {
                float a = As[k][row * 4 + i];
                ull aa = pack2(a, a);
                fma2(acc[i][0], aa, b01);
                fma2(acc[i][1], aa, b23);
            }
        }
        __syncthreads();
    }

    const float alpha = *a1p;
#pragma unroll
    for (int i = 0; i < 4; i++) {
        int d = d0 + row * 4 + i;
        float bb = bias1[d];
        float2 v01 = unpack2(acc[i][0]), v23 = unpack2(acc[i][1]);
        float h0 = v01.x + bb, h1 = v01.y + bb, h2 = v23.x + bb, h3 = v23.y + bb;
        float4 o;
        o.x = h0 >= 0.f ? h0 : alpha * h0;
        o.y = h1 >= 0.f ? h1 : alpha * h1;
        o.z = h2 >= 0.f ? h2 : alpha * h2;
        o.w = h3 >= 0.f ? h3 : alpha * h3;

        float s = o.x + o.y + o.z + o.w;
        float q = o.x * o.x + o.y * o.y + o.z * o.z + o.w * o.w;
#pragma unroll
        for (int off = 8; off >= 1; off >>= 1) {
            s += __shfl_xor_sync(0xffffffffu, s, off, 16);
            q += __shfl_xor_sync(0xffffffffu, q, off, 16);
        }
        if (col == 0) {
            atomicAdd(&g_sum[d], s);
            atomicAdd(&g_sumsq[d], q);
        }
        *(float4*)(g_y1 + (b * Dd + d) * Tt + t0 + col * 4) = o;
    }
}

// ============================================================================
// finalize1: per-channel BN params for stage 1, reset accumulators.
// ============================================================================
__global__ void finalize1_kernel(const float* __restrict__ gamma,
                                 const float* __restrict__ beta)
{
    int d = threadIdx.x;
    float mean = g_sum[d] * (1.f / NBTf);
    float var  = g_sumsq[d] * (1.f / NBTf) - mean * mean;
    float sc = gamma[d] * rsqrtf(var + EPSf);
    g_scale1[d] = sc;
    g_shift1[d] = beta[d] - mean * sc;
    g_sum[d] = 0.f;
    g_sumsq[d] = 0.f;
}

// ============================================================================
// Kernel 2: BN-apply + dilated depthwise conv (K=3, 'same') + PReLU + stats.
// One (t-chunk, d, b) per block, streaming along T.
// ============================================================================
__global__ __launch_bounds__(256) void dw_kernel(
    const float* __restrict__ wd, const float* __restrict__ bd,
    const float* __restrict__ a2p, int dil)
{
    const int d = blockIdx.y, b = blockIdx.z;
    const int tstart = blockIdx.x * 1000;
    const float* in  = g_y1 + (b * Dd + d) * Tt;
    float* outp      = g_z  + (b * Dd + d) * Tt;
    const float w0 = wd[d * 3 + 0], w1 = wd[d * 3 + 1], w2v = wd[d * 3 + 2];
    const float sc = g_scale1[d], sh = g_shift1[d];
    const float bias = bd[d], alpha = *a2p;

    float ls = 0.f, lq = 0.f;
    for (int t = tstart + threadIdx.x; t < tstart + 1000; t += 256) {
        float acc = bias;
        int tm = t - dil, tp = t + dil;
        if (tm >= 0)  acc += w0  * (in[tm] * sc + sh);
        acc            += w1  * (in[t]  * sc + sh);
        if (tp < Tt)  acc += w2v * (in[tp] * sc + sh);
        float v = acc >= 0.f ? acc : alpha * acc;
        outp[t] = v;
        ls += v; lq += v * v;
    }
#pragma unroll
    for (int off = 16; off >= 1; off >>= 1) {
        ls += __shfl_xor_sync(0xffffffffu, ls, off);
        lq += __shfl_xor_sync(0xffffffffu, lq, off);
    }
    __shared__ float ss[8], sq[8];
    int wid = threadIdx.x >> 5, lane = threadIdx.x & 31;
    if (lane == 0) { ss[wid] = ls; sq[wid] = lq; }
    __syncthreads();
    if (threadIdx.x == 0) {
        float S = 0.f, Q = 0.f;
#pragma unroll
        for (int w = 0; w < 8; w++) { S += ss[w]; Q += sq[w]; }
        atomicAdd(&g_sum[d], S);
        atomicAdd(&g_sumsq[d], Q);
    }
}

// ============================================================================
// finalize2: BN params for stage 2, fold shift into effective output bias
// biaseff[c] = b2[c] + sum_d w2[c,d]*shift2[d]; reset accumulators.
// ============================================================================
__global__ void finalize2_kernel(const float* __restrict__ gamma,
                                 const float* __restrict__ beta,
                                 const float* __restrict__ w2,
                                 const float* __restrict__ b2)
{
    int d = threadIdx.x;
    float mean = g_sum[d] * (1.f / NBTf);
    float var  = g_sumsq[d] * (1.f / NBTf) - mean * mean;
    float sc = gamma[d] * rsqrtf(var + EPSf);
    g_scale2[d] = sc;
    g_shift2[d] = beta[d] - mean * sc;
    g_sum[d] = 0.f;
    g_sumsq[d] = 0.f;
    __syncthreads();
    if (d < Cc) {
        float acc = b2[d];
        for (int j = 0; j < Dd; j++) acc += w2[d * Dd + j] * g_shift2[j];
        g_biaseff[d] = acc;
    }
}

// ============================================================================
// Kernel 3: 1x1 conv D->C with folded BN scale (applied to W tile on load)
// and folded bias; adds residual x and writes d_out on the last layer.
// ============================================================================
__global__ __launch_bounds__(256) void gemm2_kernel(
    const float* __restrict__ W2, const float* __restrict__ Xres,
    float* __restrict__ Out, int last)
{
    __shared__ float As[64][65];   // As[k][m] = W2[c0+m][k0+k] * scale2[k0+k]
    __shared__ float Bs[64][64];   // Bs[k][n] = Z[b][k0+k][t0+n]

    const int tid = threadIdx.x;
    const int row = tid >> 4, col = tid & 15;
    const int t0 = blockIdx.x * 64;
    const int c0 = blockIdx.y * 64;
    const int b  = blockIdx.z;

    ull acc[4][2];
#pragma unroll
    for (int i = 0; i < 4; i++) { acc[i][0] = 0ULL; acc[i][1] = 0ULL; }

    for (int k0 = 0; k0 < Dd; k0 += 64) {
#pragma unroll
        for (int p = 0; p < 4; p++) {
            int idx = p * 256 + tid;
            int k4 = idx & 15, m = idx >> 4;
            float4 v  = *(const float4*)(W2 + (c0 + m) * Dd + k0 + k4 * 4);
            float4 sc = *(const float4*)(g_scale2 + k0 + k4 * 4);
            As[k4 * 4 + 0][m] = v.x * sc.x;
            As[k4 * 4 + 1][m] = v.y * sc.y;
            As[k4 * 4 + 2][m] = v.z * sc.z;
            As[k4 * 4 + 3][m] = v.w * sc.w;
        }
#pragma unroll
        for (int p = 0; p < 4; p++) {
            int idx = p * 256 + tid;
            int n4 = idx & 15, kk = idx >> 4;
            *(float4*)(&Bs[kk][n4 * 4]) =
                *(const float4*)(g_z + (b * Dd + k0 + kk) * Tt + t0 + n4 * 4);
        }
        __syncthreads();
#pragma unroll 8
        for (int k = 0; k < 64; k++) {
            float4 bv = *(const float4*)(&Bs[k][col * 4]);
            ull b01 = pack2(bv.x, bv.y), b23 = pack2(bv.z, bv.w);
#pragma unroll
            for (int i = 0; i < 4; i++) {
                float a = As[k][row * 4 + i];
                ull aa = pack2(a, a);
                fma2(acc[i][0], aa, b01);
                fma2(acc[i][1], aa, b23);
            }
        }
        __syncthreads();
    }

    float* O = last ? Out : g_h;
#pragma unroll
    for (int i = 0; i < 4; i++) {
        int c = c0 + row * 4 + i;
        float bb = g_biaseff[c];
        float2 v01 = unpack2(acc[i][0]), v23 = unpack2(acc[i][1]);
        float4 o;
        o.x = v01.x + bb; o.y = v01.y + bb; o.z = v23.x + bb; o.w = v23.y + bb;
        if (last) {
            float4 xr = *(const float4*)(Xres + (b * Cc + c) * Tt + t0 + col * 4);
            o.x += xr.x; o.y += xr.y; o.z += xr.z; o.w += xr.w;
        }
        *(float4*)(O + (b * Cc + c) * Tt + t0 + col * 4) = o;
    }
}

// ============================================================================
// Host driver — graph-capturable: 20 kernel launches, no sync, no allocs.
// ============================================================================
extern "C" void kernel_launch(void* const* d_in, const int* in_sizes, int n_in,
                              void* d_out, int out_size)
{
    const float* x   = (const float*)d_in[0];
    const float* w1  = (const float*)d_in[1];
    const float* b1  = (const float*)d_in[2];
    const float* a1  = (const float*)d_in[3];
    const float* g1  = (const float*)d_in[4];
    const float* be1 = (const float*)d_in[5];
    const float* wd  = (const float*)d_in[6];
    const float* bd  = (const float*)d_in[7];
    const float* a2  = (const float*)d_in[8];
    const float* g2  = (const float*)d_in[9];
    const float* be2 = (const float*)d_in[10];
    const float* w2  = (const float*)d_in[11];
    const float* b2  = (const float*)d_in[12];
    float* out = (float*)d_out;

    dim3 gg1(125, 8, 8);     // t-tiles, d-tiles, batch
    dim3 gg2(125, 2, 8);     // t-tiles, c-tiles, batch
    dim3 gdw(8, 512, 8);     // t-chunks, d, batch

    for (int l = 0; l < Ll; l++) {
        gemm1_kernel<<<gg1, 256>>>(x, w1 + l * Dd * Cc, b1 + l * Dd, a1 + l,
                                   l > 0 ? 1 : 0);
        finalize1_kernel<<<1, 512>>>(g1 + l * Dd, be1 + l * Dd);
        dw_kernel<<<gdw, 256>>>(wd + l * Dd * 3, bd + l * Dd, a2 + l, 1 << l);
        finalize2_kernel<<<1, 512>>>(g2 + l * Dd, be2 + l * Dd,
                                     w2 + l * Cc * Dd, b2 + l * Cc);
        gemm2_kernel<<<gg2, 256>>>(w2 + l * Cc * Dd, x, out,
                                   l == Ll - 1 ? 1 : 0);
    }
}

// round 7
// speedup vs baseline: 2.4250x; 2.4250x over previous
#include <cuda_runtime.h>
#include <cuda_bf16.h>
#include <cstdint>

#define Bq 8
#define Cc 128
#define Dd 512
#define Tt 8000
#define Ll 4
#define EPSf 1e-5f
#define NBTf 64000.0f

typedef unsigned int u32;
typedef unsigned long long u64;
typedef __nv_bfloat16 bf16;

// ---------------- device scratch (no allocations allowed) ----------------
__device__ float g_y1[Bq * Dd * Tt];                            // 131 MB fp32
__device__ bf16  g_zs_hi[Bq * Dd * Tt], g_zs_lo[Bq * Dd * Tt];  // 65.5 MB each
__device__ bf16  g_hs_hi[Bq * Cc * Tt], g_hs_lo[Bq * Cc * Tt];  // 16.4 MB each
__device__ bf16  g_w1s_hi[Ll * Dd * Cc], g_w1s_lo[Ll * Dd * Cc];
__device__ bf16  g_w2s_hi[Cc * Dd], g_w2s_lo[Cc * Dd];
__device__ float g_sum[Dd], g_sumsq[Dd];
__device__ float g_scale1[Dd], g_shift1[Dd];
__device__ float g_scale2[Dd], g_shift2[Dd];
__device__ float g_biaseff[Cc];

// ---------------- helpers ----------------
__device__ __forceinline__ u32 smem_u32(const void* p) {
    u32 a; asm("{ .reg .u64 t; cvta.to.shared.u64 t, %1; cvt.u32.u64 %0, t; }"
               : "=r"(a) : "l"(p));
    return a;
}
__device__ __forceinline__ void split2(float v, bf16& h, bf16& l) {
    h = __float2bfloat16(v);
    l = __float2bfloat16(v - __bfloat162float(h));
}
__device__ __forceinline__ u32 pack_hi2(float v0, float v1, u32& lo_out) {
    bf16 h0, l0, h1, l1;
    split2(v0, h0, l0); split2(v1, h1, l1);
    lo_out = (u32)__bfloat16_as_ushort(l0) | ((u32)__bfloat16_as_ushort(l1) << 16);
    return (u32)__bfloat16_as_ushort(h0) | ((u32)__bfloat16_as_ushort(h1) << 16);
}

#define CPA16(dst, src) \
    asm volatile("cp.async.cg.shared.global [%0], [%1], 16;" :: "r"(dst), "l"(src))
#define CPA_COMMIT() asm volatile("cp.async.commit_group;" ::: "memory")
#define CPA_WAIT1()  asm volatile("cp.async.wait_group 1;" ::: "memory")
#define CPA_WAIT0()  asm volatile("cp.async.wait_group 0;" ::: "memory")

#define LDSM_X4(r, a) \
    asm volatile("ldmatrix.sync.aligned.m8n8.x4.shared.b16 {%0,%1,%2,%3}, [%4];" \
        : "=r"((r)[0]), "=r"((r)[1]), "=r"((r)[2]), "=r"((r)[3]) : "r"(a))
#define LDSM_X4T(r, a) \
    asm volatile("ldmatrix.sync.aligned.m8n8.x4.trans.shared.b16 {%0,%1,%2,%3}, [%4];" \
        : "=r"((r)[0]), "=r"((r)[1]), "=r"((r)[2]), "=r"((r)[3]) : "r"(a))

#define MMA16816(d, a, b0, b1) \
    asm volatile("mma.sync.aligned.m16n8k16.row.col.f32.bf16.bf16.f32 " \
        "{%0,%1,%2,%3}, {%4,%5,%6,%7}, {%8,%9}, {%0,%1,%2,%3};" \
        : "+f"((d)[0]), "+f"((d)[1]), "+f"((d)[2]), "+f"((d)[3]) \
        : "r"((a)[0]), "r"((a)[1]), "r"((a)[2]), "r"((a)[3]), "r"(b0), "r"(b1))

// smem stage: A(hi|lo packed, 128 rows x 128B) 16KB, Bhi 4KB, Blo 4KB = 24KB
#define STAGE_BYTES 24576
#define B_OFF       16384

// ============================================================================
// GEMM: C[m, t0:t0+64] = sum_k A[m,k] * B[k,t]  via bf16 split, 3-pass mma.sync
// mode 0: conv1  A = w1 splits (K=128), B = h splits; epi: bias+prelu+stats -> g_y1
// mode 1: conv2  A = w2*scale2 splits (K=512), B = z splits;
//                epi: biaseff (+x -> out on last, else split -> h)
// ============================================================================
__global__ __launch_bounds__(256) void gemm_tc_kernel(
    int mode, int last, int layer,
    const float* __restrict__ bias1, const float* __restrict__ alphap,
    const float* __restrict__ Xres, float* __restrict__ OutF)
{
    __shared__ __align__(1024) char smem[2 * STAGE_BYTES];
    const u32 sb = smem_u32(smem);
    const int tid = threadIdx.x;
    const int lane = tid & 31, wid = tid >> 5;
    const int wm = wid >> 1, wn = wid & 1;       // warp grid 4 x 2
    const int t0 = blockIdx.x * 64;
    const int m0 = blockIdx.y * 128;
    const int b  = blockIdx.z;

    const bf16 *Ah, *Al, *Bh, *Bl;
    int K;
    if (mode == 0) {
        Ah = g_w1s_hi + (size_t)layer * Dd * Cc;
        Al = g_w1s_lo + (size_t)layer * Dd * Cc;
        Bh = g_hs_hi + (size_t)b * Cc * Tt;
        Bl = g_hs_lo + (size_t)b * Cc * Tt;
        K = Cc;
    } else {
        Ah = g_w2s_hi; Al = g_w2s_lo;
        Bh = g_zs_hi + (size_t)b * Dd * Tt;
        Bl = g_zs_lo + (size_t)b * Dd * Tt;
        K = Dd;
    }
    const int niter = K / 32;

    // ---- cp.async source/dst precompute ----
    // A: 128 rows x 8 chunks/row (cols 0-3 = hi k0..31, cols 4-7 = lo k0..31)
    //    = 1024 chunks -> 4 per thread.
    u32 a_dst[4]; const bf16* a_src[4];
#pragma unroll
    for (int i = 0; i < 4; i++) {
        int c = tid + i * 256;
        int m = c >> 3, q = c & 7;
        u32 off = (u32)m * 128 + (u32)q * 16;
        a_dst[i] = sb + (off ^ ((off >> 3) & 0x70));
        a_src[i] = (q < 4 ? Ah : Al) + (size_t)(m0 + m) * K + (q & 3) * 8;
    }
    // B: 2 planes x 32 k-rows x 8 chunks/row = 512 chunks -> 2 per thread.
    u32 b_dst[2]; const bf16* b_src[2];
#pragma unroll
    for (int i = 0; i < 2; i++) {
        int c = tid + i * 256;
        int plane = c >> 8, k = (c >> 3) & 31, q = c & 7;
        u32 off = (u32)k * 128 + (u32)q * 16;
        b_dst[i] = sb + B_OFF + (u32)plane * 4096 + (off ^ ((off >> 3) & 0x70));
        b_src[i] = (plane ? Bl : Bh) + (size_t)k * Tt + t0 + q * 8;
    }

    float acc[2][4][4];
#pragma unroll
    for (int i = 0; i < 2; i++)
#pragma unroll
        for (int j = 0; j < 4; j++)
#pragma unroll
            for (int r = 0; r < 4; r++) acc[i][j][r] = 0.f;

    // prologue: stage 0
#pragma unroll
    for (int i = 0; i < 4; i++) CPA16(a_dst[i], a_src[i]);
#pragma unroll
    for (int i = 0; i < 2; i++) CPA16(b_dst[i], b_src[i]);
    CPA_COMMIT();

    const u32 aswx = ((u32)(lane & 7)) << 4;

    for (int it = 0; it < niter; it++) {
        const int stage = it & 1;
        if (it + 1 < niter) {
            const u32 so = (stage ^ 1) ? STAGE_BYTES : 0;
            const int kadv = (it + 1) * 32;
#pragma unroll
            for (int i = 0; i < 4; i++) CPA16(a_dst[i] + so, a_src[i] + kadv);
#pragma unroll
            for (int i = 0; i < 2; i++)
                CPA16(b_dst[i] + so, b_src[i] + (size_t)kadv * Tt);
            CPA_COMMIT();
            CPA_WAIT1();
        } else {
            CPA_WAIT0();
        }
        __syncthreads();

        const u32 Abase  = sb + (stage ? STAGE_BYTES : 0);
        const u32 Bhbase = Abase + B_OFF;
        const u32 Blbase = Bhbase + 4096;

#pragma unroll
        for (int kk = 0; kk < 2; kk++) {
            u32 ahi[2][4], alo[2][4], bhi[2][4], blo[2][4];
#pragma unroll
            for (int i = 0; i < 2; i++) {
                u32 row = (u32)(wm * 32 + i * 16 + (lane & 15));
                u32 colb = (u32)(kk * 32 + ((lane >> 4) << 4));
                u32 offh = row * 128 + colb;
                LDSM_X4(ahi[i], Abase + (offh ^ aswx));
                LDSM_X4(alo[i], Abase + ((offh + 64) ^ aswx));
            }
#pragma unroll
            for (int j = 0; j < 2; j++) {
                u32 k = (u32)(kk * 16 + ((lane >> 3) & 1) * 8 + (lane & 7));
                u32 n = (u32)(wn * 32 + j * 16 + (lane >> 4) * 8);
                u32 off = k * 128 + n * 2;
                u32 sw = off ^ aswx;   // k&7 == lane&7
                LDSM_X4T(bhi[j], Bhbase + sw);
                LDSM_X4T(blo[j], Blbase + sw);
            }
#pragma unroll
            for (int i = 0; i < 2; i++) {
#pragma unroll
                for (int jn = 0; jn < 4; jn++) {
                    const int jg = jn >> 1, jr = (jn & 1) * 2;
                    MMA16816(acc[i][jn], ahi[i], bhi[jg][jr], bhi[jg][jr + 1]);
                    MMA16816(acc[i][jn], ahi[i], blo[jg][jr], blo[jg][jr + 1]);
                    MMA16816(acc[i][jn], alo[i], bhi[jg][jr], bhi[jg][jr + 1]);
                }
            }
        }
        __syncthreads();
    }

    // ---- epilogue ----
    const int colbase = t0 + wn * 32 + (lane & 3) * 2;
    if (mode == 0) {
        const float alpha = *alphap;
#pragma unroll
        for (int i = 0; i < 2; i++)
#pragma unroll
            for (int h = 0; h < 2; h++) {
                const int d = m0 + wm * 32 + i * 16 + (lane >> 2) + h * 8;
                const float bb = bias1[d];
                float s = 0.f, q = 0.f;
                float* yp = g_y1 + ((size_t)b * Dd + d) * Tt + colbase;
#pragma unroll
                for (int jn = 0; jn < 4; jn++) {
                    float v0 = acc[i][jn][h * 2] + bb;
                    float v1 = acc[i][jn][h * 2 + 1] + bb;
                    v0 = v0 >= 0.f ? v0 : alpha * v0;
                    v1 = v1 >= 0.f ? v1 : alpha * v1;
                    s += v0 + v1;
                    q += v0 * v0 + v1 * v1;
                    float2 st; st.x = v0; st.y = v1;
                    *(float2*)(yp + jn * 8) = st;
                }
                s += __shfl_xor_sync(0xffffffffu, s, 1);
                s += __shfl_xor_sync(0xffffffffu, s, 2);
                q += __shfl_xor_sync(0xffffffffu, q, 1);
                q += __shfl_xor_sync(0xffffffffu, q, 2);
                if ((lane & 3) == 0) {
                    atomicAdd(&g_sum[d], s);
                    atomicAdd(&g_sumsq[d], q);
                }
            }
    } else {
#pragma unroll
        for (int i = 0; i < 2; i++)
#pragma unroll
            for (int h = 0; h < 2; h++) {
                const int c = wm * 32 + i * 16 + (lane >> 2) + h * 8;
                const float bb = g_biaseff[c];
                if (last) {
                    float* op = OutF + ((size_t)b * Cc + c) * Tt + colbase;
                    const float* xp = Xres + ((size_t)b * Cc + c) * Tt + colbase;
#pragma unroll
                    for (int jn = 0; jn < 4; jn++) {
                        float2 xv = *(const float2*)(xp + jn * 8);
                        float2 st;
                        st.x = acc[i][jn][h * 2] + bb + xv.x;
                        st.y = acc[i][jn][h * 2 + 1] + bb + xv.y;
                        *(float2*)(op + jn * 8) = st;
                    }
                } else {
                    u32* hp = (u32*)(g_hs_hi + ((size_t)b * Cc + c) * Tt + colbase);
                    u32* lp = (u32*)(g_hs_lo + ((size_t)b * Cc + c) * Tt + colbase);
#pragma unroll
                    for (int jn = 0; jn < 4; jn++) {
                        float v0 = acc[i][jn][h * 2] + bb;
                        float v1 = acc[i][jn][h * 2 + 1] + bb;
                        u32 lw, hw = pack_hi2(v0, v1, lw);
                        hp[jn * 4] = hw;
                        lp[jn * 4] = lw;
                    }
                }
            }
    }
}

// ============================================================================
// finalize1: BN1 params from stats, reset accumulators.
// ============================================================================
__global__ void finalize1_kernel(const float* __restrict__ gamma,
                                 const float* __restrict__ beta)
{
    int d = threadIdx.x;
    float mean = g_sum[d] * (1.f / NBTf);
    float var  = g_sumsq[d] * (1.f / NBTf) - mean * mean;
    float sc = gamma[d] * rsqrtf(var + EPSf);
    g_scale1[d] = sc;
    g_shift1[d] = beta[d] - mean * sc;
    g_sum[d] = 0.f;
    g_sumsq[d] = 0.f;
}

// ============================================================================
// dw: BN1-apply + dilated depthwise K=3 + PReLU + BN2 stats; z -> hi/lo bf16.
// ============================================================================
__global__ __launch_bounds__(256) void dw_kernel(
    const float* __restrict__ wd, const float* __restrict__ bd,
    const float* __restrict__ a2p, int dil)
{
    const int d = blockIdx.y, b = blockIdx.z;
    const int tstart = blockIdx.x * 1000;
    const size_t base = ((size_t)b * Dd + d) * Tt;
    const float* in = g_y1 + base;
    const float w0 = wd[d * 3 + 0], w1 = wd[d * 3 + 1], w2v = wd[d * 3 + 2];
    const float sc = g_scale1[d], sh = g_shift1[d];
    const float bias = bd[d], alpha = *a2p;

    float ls = 0.f, lq = 0.f;
    for (int p = threadIdx.x; p < 500; p += 256) {
        const int t = tstart + 2 * p;
        float v[2];
#pragma unroll
        for (int e = 0; e < 2; e++) {
            const int tt = t + e;
            float acc = bias;
            int tm = tt - dil, tp = tt + dil;
            if (tm >= 0) acc += w0  * (in[tm] * sc + sh);
            acc           += w1  * (in[tt] * sc + sh);
            if (tp < Tt) acc += w2v * (in[tp] * sc + sh);
            v[e] = acc >= 0.f ? acc : alpha * acc;
            ls += v[e]; lq += v[e] * v[e];
        }
        u32 lw, hw = pack_hi2(v[0], v[1], lw);
        *(u32*)(g_zs_hi + base + t) = hw;
        *(u32*)(g_zs_lo + base + t) = lw;
    }
#pragma unroll
    for (int off = 16; off >= 1; off >>= 1) {
        ls += __shfl_xor_sync(0xffffffffu, ls, off);
        lq += __shfl_xor_sync(0xffffffffu, lq, off);
    }
    __shared__ float ss[8], sq[8];
    int wi = threadIdx.x >> 5, lane = threadIdx.x & 31;
    if (lane == 0) { ss[wi] = ls; sq[wi] = lq; }
    __syncthreads();
    if (threadIdx.x == 0) {
        float S = 0.f, Q = 0.f;
#pragma unroll
        for (int w = 0; w < 8; w++) { S += ss[w]; Q += sq[w]; }
        atomicAdd(&g_sum[d], S);
        atomicAdd(&g_sumsq[d], Q);
    }
}

// ============================================================================
// finalize2a: BN2 params, reset accumulators.
// ============================================================================
__global__ void finalize2a_kernel(const float* __restrict__ gamma,
                                  const float* __restrict__ beta)
{
    int d = threadIdx.x;
    float mean = g_sum[d] * (1.f / NBTf);
    float var  = g_sumsq[d] * (1.f / NBTf) - mean * mean;
    float sc = gamma[d] * rsqrtf(var + EPSf);
    g_scale2[d] = sc;
    g_shift2[d] = beta[d] - mean * sc;
    g_sum[d] = 0.f;
    g_sumsq[d] = 0.f;
}

// ============================================================================
// convert_w2: W2*scale2 -> bf16 splits + effective bias (parallel dot).
// ============================================================================
__global__ __launch_bounds__(256) void convert_w2_kernel(
    const float* __restrict__ w2, const float* __restrict__ b2)
{
    const int c = blockIdx.x;
    float local = 0.f;
    for (int d = threadIdx.x; d < Dd; d += 256) {
        float w = w2[(size_t)c * Dd + d];
        bf16 h, l;
        split2(w * g_scale2[d], h, l);
        g_w2s_hi[(size_t)c * Dd + d] = h;
        g_w2s_lo[(size_t)c * Dd + d] = l;
        local += w * g_shift2[d];
    }
#pragma unroll
    for (int off = 16; off >= 1; off >>= 1)
        local += __shfl_xor_sync(0xffffffffu, local, off);
    __shared__ float sred[8];
    int wi = threadIdx.x >> 5, lane = threadIdx.x & 31;
    if (lane == 0) sred[wi] = local;
    __syncthreads();
    if (threadIdx.x == 0) {
        float tot = 0.f;
#pragma unroll
        for (int w = 0; w < 8; w++) tot += sred[w];
        g_biaseff[c] = b2[c] + tot;
    }
}

// ============================================================================
// converters: x -> h splits (pairs), w1 -> splits.
// ============================================================================
__global__ void convert_x_kernel(const float* __restrict__ x)
{
    int p = blockIdx.x * 256 + threadIdx.x;
    if (p < Bq * Cc * Tt / 2) {
        float2 v = ((const float2*)x)[p];
        u32 lw, hw = pack_hi2(v.x, v.y, lw);
        ((u32*)g_hs_hi)[p] = hw;
        ((u32*)g_hs_lo)[p] = lw;
    }
}
__global__ void convert_w1_kernel(const float* __restrict__ w1)
{
    int i = blockIdx.x * 256 + threadIdx.x;
    if (i < Ll * Dd * Cc) {
        bf16 h, l;
        split2(w1[i], h, l);
        g_w1s_hi[i] = h;
        g_w1s_lo[i] = l;
    }
}

// ============================================================================
// Host driver — graph-capturable: 26 kernel launches, no sync, no allocs.
// ============================================================================
extern "C" void kernel_launch(void* const* d_in, const int* in_sizes, int n_in,
                              void* d_out, int out_size)
{
    const float* x   = (const float*)d_in[0];
    const float* w1  = (const float*)d_in[1];
    const float* b1  = (const float*)d_in[2];
    const float* a1  = (const float*)d_in[3];
    const float* g1  = (const float*)d_in[4];
    const float* be1 = (const float*)d_in[5];
    const float* wd  = (const float*)d_in[6];
    const float* bd  = (const float*)d_in[7];
    const float* a2  = (const float*)d_in[8];
    const float* g2  = (const float*)d_in[9];
    const float* be2 = (const float*)d_in[10];
    const float* w2  = (const float*)d_in[11];
    const float* b2  = (const float*)d_in[12];
    float* out = (float*)d_out;

    convert_x_kernel<<<(Bq * Cc * Tt / 2 + 255) / 256, 256>>>(x);
    convert_w1_kernel<<<(Ll * Dd * Cc + 255) / 256, 256>>>(w1);

    dim3 gg1(125, 4, 8);   // t-tiles, m-tiles (512/128), batch
    dim3 gg2(125, 1, 8);   // t-tiles, m-tiles (128/128), batch
    dim3 gdw(8, 512, 8);

    for (int l = 0; l < Ll; l++) {
        gemm_tc_kernel<<<gg1, 256>>>(0, 0, l, b1 + l * Dd, a1 + l, x, nullptr);
        finalize1_kernel<<<1, 512>>>(g1 + l * Dd, be1 + l * Dd);
        dw_kernel<<<gdw, 256>>>(wd + l * Dd * 3, bd + l * Dd, a2 + l, 1 << l);
        finalize2a_kernel<<<1, 512>>>(g2 + l * Dd, be2 + l * Dd);
        convert_w2_kernel<<<128, 256>>>(w2 + l * Cc * Dd, b2 + l * Cc);
        gemm_tc_kernel<<<gg2, 256>>>(1, l == Ll - 1 ? 1 : 0, l,
                                     nullptr, nullptr, x, out);
    }
}